// round 9
// baseline (speedup 1.0000x reference)
#include <cuda_runtime.h>
#include <math.h>

#define BATCH  4
#define DMODEL 1024
#define LSEQ   2048
#define HEADS  16
#define DH     64

// Scratch: Q,K in [B][H][dh][L] (L contiguous), V in [B][H][L][dh] (dh contiguous)
__device__ float g_Q[(size_t)BATCH * HEADS * DH * LSEQ];
__device__ float g_K[(size_t)BATCH * HEADS * DH * LSEQ];
__device__ float g_V[(size_t)BATCH * HEADS * LSEQ * DH];

// ---------------------------------------------------------------------------
// QKV projection: out[o, b, l] = sum_d W[o,d] * x[b,d,l], o in [0,3072)
//   o <  1024 -> Q (scaled by dh^-0.5)
//   o <  2048 -> K
//   else      -> V
// Classic 128x128x8 SGEMM, 256 threads, 8x8 per-thread tile.
// ---------------------------------------------------------------------------
#define PBM 128
#define PBN 128
#define PBK 8
#define PST 132  // padded shared stride

__global__ __launch_bounds__(256, 2)
void proj_kernel(const float* __restrict__ x, const float* __restrict__ Wq,
                 const float* __restrict__ Wkv)
{
    __shared__ float As[PBK][PST];  // [d][o]
    __shared__ float Bs[PBK][PST];  // [d][l]

    const int b  = blockIdx.z;
    const int o0 = blockIdx.y * PBM;
    const int l0 = blockIdx.x * PBN;
    const int t  = threadIdx.x;
    const int tx = t & 15;
    const int ty = t >> 4;

    const float* W  = (o0 < DMODEL) ? (Wq + (size_t)o0 * DMODEL)
                                    : (Wkv + (size_t)(o0 - DMODEL) * DMODEL);
    const float* xb = x + (size_t)b * DMODEL * LSEQ;

    const int wrow = t >> 1;          // 0..127 within tile
    const int wd4  = (t & 1) * 4;     // 0 or 4
    const int xrow = t >> 5;          // 0..7
    const int xc4  = (t & 31) * 4;    // 0..124

    float acc[8][8];
    #pragma unroll
    for (int i = 0; i < 8; i++)
        #pragma unroll
        for (int j = 0; j < 8; j++) acc[i][j] = 0.f;

    for (int dk = 0; dk < DMODEL; dk += PBK) {
        float4 wv = *(const float4*)(W + (size_t)wrow * DMODEL + dk + wd4);
        As[wd4 + 0][wrow] = wv.x;
        As[wd4 + 1][wrow] = wv.y;
        As[wd4 + 2][wrow] = wv.z;
        As[wd4 + 3][wrow] = wv.w;
        *(float4*)&Bs[xrow][xc4] =
            *(const float4*)(xb + (size_t)(dk + xrow) * LSEQ + l0 + xc4);
        __syncthreads();

        #pragma unroll
        for (int d = 0; d < PBK; d++) {
            float a[8], bb[8];
            *(float4*)(a)      = *(float4*)&As[d][8 * ty];
            *(float4*)(a + 4)  = *(float4*)&As[d][8 * ty + 4];
            *(float4*)(bb)     = *(float4*)&Bs[d][8 * tx];
            *(float4*)(bb + 4) = *(float4*)&Bs[d][8 * tx + 4];
            #pragma unroll
            for (int i = 0; i < 8; i++)
                #pragma unroll
                for (int j = 0; j < 8; j++)
                    acc[i][j] += a[i] * bb[j];
        }
        __syncthreads();
    }

    // Epilogue
    #pragma unroll
    for (int i = 0; i < 8; i++) {
        const int o = o0 + 8 * ty + i;
        const int lbase = l0 + 8 * tx;
        if (o < DMODEL) {
            const int h = o >> 6, d = o & 63;
            float* dst = g_Q + (((size_t)(b * HEADS + h) * DH + d) << 11) + lbase;
            float4 v0 = make_float4(acc[i][0] * 0.125f, acc[i][1] * 0.125f,
                                    acc[i][2] * 0.125f, acc[i][3] * 0.125f);
            float4 v1 = make_float4(acc[i][4] * 0.125f, acc[i][5] * 0.125f,
                                    acc[i][6] * 0.125f, acc[i][7] * 0.125f);
            *(float4*)(dst) = v0;
            *(float4*)(dst + 4) = v1;
        } else if (o < 2 * DMODEL) {
            const int oo = o - DMODEL;
            const int h = oo >> 6, d = oo & 63;
            float* dst = g_K + (((size_t)(b * HEADS + h) * DH + d) << 11) + lbase;
            *(float4*)(dst)     = make_float4(acc[i][0], acc[i][1], acc[i][2], acc[i][3]);
            *(float4*)(dst + 4) = make_float4(acc[i][4], acc[i][5], acc[i][6], acc[i][7]);
        } else {
            const int oo = o - 2 * DMODEL;
            const int h = oo >> 6, d = oo & 63;
            float* base = g_V + ((size_t)(b * HEADS + h) * LSEQ << 6) + d;
            #pragma unroll
            for (int j = 0; j < 8; j++)
                base[(size_t)(lbase + j) << 6] = acc[i][j];
        }
    }
}

// ---------------------------------------------------------------------------
// Flash attention, fp32 SIMT. One block = (b, h, 64-row q tile).
// Shared tiles: Qts[d][q], Kts[d][k] (transposed: natural from [dh][L] layout),
// Vs[k][d], Sts[k][q]. 256 threads, each owns a 4x4 (q x d) output block.
// ---------------------------------------------------------------------------
#define SST 68
#define ATTN_SMEM ((4 * 64 * SST + 3 * 64) * (int)sizeof(float))

__global__ __launch_bounds__(256)
void attn_kernel(const int* __restrict__ mask, float* __restrict__ out)
{
    extern __shared__ float sm[];
    float* Qts     = sm;                 // [d][q]  64xSST
    float* Kts     = Qts + 64 * SST;     // [d][k]
    float* Vs      = Kts + 64 * SST;     // [k][d]
    float* Sts     = Vs  + 64 * SST;     // [k][q]  (reused as O[d][q] at end)
    float* maskf   = Sts + 64 * SST;     // [64]
    float* alpha_s = maskf + 64;         // [64]
    float* l_s     = alpha_s + 64;       // [64]

    const int t  = threadIdx.x;
    const int tx = t & 15;
    const int ty = t >> 4;
    const int q0 = blockIdx.x * 64;
    const int bh = blockIdx.y;
    const int b  = bh >> 4;
    const int h  = bh & 15;

    const float* Qb = g_Q + (size_t)bh * DH * LSEQ;
    const float* Kb = g_K + (size_t)bh * DH * LSEQ;
    const float* Vb = g_V + (size_t)bh * LSEQ * DH;

    // Load Q tile: Qts[d][q] <- Qb[d][q0+q]  (coalesced, conflict-free)
    #pragma unroll
    for (int r = 0; r < 4; r++) {
        int f = t + r * 256;            // float4 index 0..1023
        int row = f >> 4, c = (f & 15) * 4;
        *(float4*)&Qts[row * SST + c] =
            *(const float4*)(Qb + (size_t)row * LSEQ + q0 + c);
    }

    float acc[4][4];
    #pragma unroll
    for (int i = 0; i < 4; i++)
        #pragma unroll
        for (int j = 0; j < 4; j++) acc[i][j] = 0.f;

    float m_run = __int_as_float(0xff800000);  // -inf
    float l_run = 0.f;

    for (int k0 = 0; k0 < LSEQ; k0 += 64) {
        __syncthreads();  // previous-iter consumers done (also publishes Qts on iter 0)

        // Load K tile [d][k], V tile [k][d], mask
        #pragma unroll
        for (int r = 0; r < 4; r++) {
            int f = t + r * 256;
            int row = f >> 4, c = (f & 15) * 4;
            *(float4*)&Kts[row * SST + c] =
                *(const float4*)(Kb + (size_t)row * LSEQ + k0 + c);
            *(float4*)&Vs[row * SST + c] =
                *(const float4*)(Vb + ((size_t)(k0 + row) << 6) + c);
        }
        if (t < 64) maskf[t] = (float)mask[b * LSEQ + k0 + t];
        __syncthreads();

        // S = Q K^T over dh, thread block (q = 4ty+i, k = 4tx+j)
        float s[4][4];
        #pragma unroll
        for (int i = 0; i < 4; i++)
            #pragma unroll
            for (int j = 0; j < 4; j++) s[i][j] = 0.f;

        #pragma unroll 16
        for (int d = 0; d < 64; d++) {
            float4 qv = *(float4*)&Qts[d * SST + 4 * ty];
            float4 kv = *(float4*)&Kts[d * SST + 4 * tx];
            s[0][0] += qv.x * kv.x; s[0][1] += qv.x * kv.y;
            s[0][2] += qv.x * kv.z; s[0][3] += qv.x * kv.w;
            s[1][0] += qv.y * kv.x; s[1][1] += qv.y * kv.y;
            s[1][2] += qv.y * kv.z; s[1][3] += qv.y * kv.w;
            s[2][0] += qv.z * kv.x; s[2][1] += qv.z * kv.y;
            s[2][2] += qv.z * kv.z; s[2][3] += qv.z * kv.w;
            s[3][0] += qv.w * kv.x; s[3][1] += qv.w * kv.y;
            s[3][2] += qv.w * kv.z; s[3][3] += qv.w * kv.w;
        }

        // Mask + store S transposed: Sts[k][q]
        #pragma unroll
        for (int j = 0; j < 4; j++) {
            float km = maskf[4 * tx + j];
            float4 sv;
            sv.x = (km > 0.5f) ? s[0][j] : -1e30f;
            sv.y = (km > 0.5f) ? s[1][j] : -1e30f;
            sv.z = (km > 0.5f) ? s[2][j] : -1e30f;
            sv.w = (km > 0.5f) ? s[3][j] : -1e30f;
            *(float4*)&Sts[(4 * tx + j) * SST + 4 * ty] = sv;
        }
        __syncthreads();

        // Online softmax: one thread per q row (consecutive addresses across t -> conflict-free)
        if (t < 64) {
            float tmax = __int_as_float(0xff800000);
            #pragma unroll 8
            for (int k = 0; k < 64; k++)
                tmax = fmaxf(tmax, Sts[k * SST + t]);
            float mn  = fmaxf(m_run, tmax);
            float al  = __expf(m_run - mn);   // 0 on first tile (-inf - finite)
            float sum = 0.f;
            #pragma unroll 8
            for (int k = 0; k < 64; k++) {
                float p = __expf(Sts[k * SST + t] - mn);
                Sts[k * SST + t] = p;
                sum += p;
            }
            l_run = l_run * al + sum;
            m_run = mn;
            alpha_s[t] = al;
        }
        __syncthreads();

        // Rescale accumulators and add P @ V (rank-1 updates over k)
        float al_i[4];
        #pragma unroll
        for (int i = 0; i < 4; i++) al_i[i] = alpha_s[4 * ty + i];
        #pragma unroll
        for (int i = 0; i < 4; i++)
            #pragma unroll
            for (int j = 0; j < 4; j++) acc[i][j] *= al_i[i];

        #pragma unroll 16
        for (int k = 0; k < 64; k++) {
            float4 pv = *(float4*)&Sts[k * SST + 4 * ty];
            float4 vv = *(float4*)&Vs[k * SST + 4 * tx];
            acc[0][0] += pv.x * vv.x; acc[0][1] += pv.x * vv.y;
            acc[0][2] += pv.x * vv.z; acc[0][3] += pv.x * vv.w;
            acc[1][0] += pv.y * vv.x; acc[1][1] += pv.y * vv.y;
            acc[1][2] += pv.y * vv.z; acc[1][3] += pv.y * vv.w;
            acc[2][0] += pv.z * vv.x; acc[2][1] += pv.z * vv.y;
            acc[2][2] += pv.z * vv.z; acc[2][3] += pv.z * vv.w;
            acc[3][0] += pv.w * vv.x; acc[3][1] += pv.w * vv.y;
            acc[3][2] += pv.w * vv.z; acc[3][3] += pv.w * vv.w;
        }
    }

    if (t < 64) l_s[t] = l_run;
    __syncthreads();

    // Normalize and stage transposed output O[d][q] into Sts
    float inv_i[4];
    #pragma unroll
    for (int i = 0; i < 4; i++) inv_i[i] = 1.f / l_s[4 * ty + i];
    #pragma unroll
    for (int j = 0; j < 4; j++) {
        float4 ov;
        ov.x = acc[0][j] * inv_i[0];
        ov.y = acc[1][j] * inv_i[1];
        ov.z = acc[2][j] * inv_i[2];
        ov.w = acc[3][j] * inv_i[3];
        *(float4*)&Sts[(4 * tx + j) * SST + 4 * ty] = ov;
    }
    __syncthreads();

    // Coalesced write: out[b][h*64+d][q0+q]
    float* ob = out + ((size_t)b * DMODEL + h * DH) * LSEQ;
    #pragma unroll
    for (int r = 0; r < 4; r++) {
        int f = t + r * 256;
        int row = f >> 4, c = (f & 15) * 4;
        *(float4*)(ob + (size_t)row * LSEQ + q0 + c) =
            *(float4*)&Sts[row * SST + c];
    }
}

// ---------------------------------------------------------------------------
extern "C" void kernel_launch(void* const* d_in, const int* in_sizes, int n_in,
                              void* d_out, int out_size)
{
    const float* x    = (const float*)d_in[0];
    const float* Wq   = (const float*)d_in[1];
    const float* Wkv  = (const float*)d_in[2];
    const int*   mask = (const int*)d_in[3];
    float* out = (float*)d_out;

    cudaFuncSetAttribute(attn_kernel,
                         cudaFuncAttributeMaxDynamicSharedMemorySize, ATTN_SMEM);

    proj_kernel<<<dim3(LSEQ / PBN, (3 * DMODEL) / PBM, BATCH), 256>>>(x, Wq, Wkv);
    attn_kernel<<<dim3(LSEQ / 64, BATCH * HEADS), 256, ATTN_SMEM>>>(mask, out);
}

// round 10
// speedup vs baseline: 1.0494x; 1.0494x over previous
#include <cuda_runtime.h>
#include <math.h>

#define BATCH  4
#define DMODEL 1024
#define LSEQ   2048
#define HEADS  16
#define DH     64

// Scratch: Q,K in [B][H][dh][L] (L contiguous), V in [B][H][L][dh] (dh contiguous)
__device__ float g_Q[(size_t)BATCH * HEADS * DH * LSEQ];
__device__ float g_K[(size_t)BATCH * HEADS * DH * LSEQ];
__device__ float g_V[(size_t)BATCH * HEADS * LSEQ * DH];

// ---------------------------------------------------------------------------
// QKV projection: unchanged from round-9 passing baseline.
// ---------------------------------------------------------------------------
#define PBM 128
#define PBN 128
#define PBK 8
#define PST 132  // padded shared stride

__global__ __launch_bounds__(256, 2)
void proj_kernel(const float* __restrict__ x, const float* __restrict__ Wq,
                 const float* __restrict__ Wkv)
{
    __shared__ float As[PBK][PST];  // [d][o]
    __shared__ float Bs[PBK][PST];  // [d][l]

    const int b  = blockIdx.z;
    const int o0 = blockIdx.y * PBM;
    const int l0 = blockIdx.x * PBN;
    const int t  = threadIdx.x;
    const int tx = t & 15;
    const int ty = t >> 4;

    const float* W  = (o0 < DMODEL) ? (Wq + (size_t)o0 * DMODEL)
                                    : (Wkv + (size_t)(o0 - DMODEL) * DMODEL);
    const float* xb = x + (size_t)b * DMODEL * LSEQ;

    const int wrow = t >> 1;          // 0..127 within tile
    const int wd4  = (t & 1) * 4;     // 0 or 4
    const int xrow = t >> 5;          // 0..7
    const int xc4  = (t & 31) * 4;    // 0..124

    float acc[8][8];
    #pragma unroll
    for (int i = 0; i < 8; i++)
        #pragma unroll
        for (int j = 0; j < 8; j++) acc[i][j] = 0.f;

    for (int dk = 0; dk < DMODEL; dk += PBK) {
        float4 wv = *(const float4*)(W + (size_t)wrow * DMODEL + dk + wd4);
        As[wd4 + 0][wrow] = wv.x;
        As[wd4 + 1][wrow] = wv.y;
        As[wd4 + 2][wrow] = wv.z;
        As[wd4 + 3][wrow] = wv.w;
        *(float4*)&Bs[xrow][xc4] =
            *(const float4*)(xb + (size_t)(dk + xrow) * LSEQ + l0 + xc4);
        __syncthreads();

        #pragma unroll
        for (int d = 0; d < PBK; d++) {
            float a[8], bb[8];
            *(float4*)(a)      = *(float4*)&As[d][8 * ty];
            *(float4*)(a + 4)  = *(float4*)&As[d][8 * ty + 4];
            *(float4*)(bb)     = *(float4*)&Bs[d][8 * tx];
            *(float4*)(bb + 4) = *(float4*)&Bs[d][8 * tx + 4];
            #pragma unroll
            for (int i = 0; i < 8; i++)
                #pragma unroll
                for (int j = 0; j < 8; j++)
                    acc[i][j] += a[i] * bb[j];
        }
        __syncthreads();
    }

    // Epilogue
    #pragma unroll
    for (int i = 0; i < 8; i++) {
        const int o = o0 + 8 * ty + i;
        const int lbase = l0 + 8 * tx;
        if (o < DMODEL) {
            const int h = o >> 6, d = o & 63;
            float* dst = g_Q + (((size_t)(b * HEADS + h) * DH + d) << 11) + lbase;
            float4 v0 = make_float4(acc[i][0] * 0.125f, acc[i][1] * 0.125f,
                                    acc[i][2] * 0.125f, acc[i][3] * 0.125f);
            float4 v1 = make_float4(acc[i][4] * 0.125f, acc[i][5] * 0.125f,
                                    acc[i][6] * 0.125f, acc[i][7] * 0.125f);
            *(float4*)(dst) = v0;
            *(float4*)(dst + 4) = v1;
        } else if (o < 2 * DMODEL) {
            const int oo = o - DMODEL;
            const int h = oo >> 6, d = oo & 63;
            float* dst = g_K + (((size_t)(b * HEADS + h) * DH + d) << 11) + lbase;
            *(float4*)(dst)     = make_float4(acc[i][0], acc[i][1], acc[i][2], acc[i][3]);
            *(float4*)(dst + 4) = make_float4(acc[i][4], acc[i][5], acc[i][6], acc[i][7]);
        } else {
            const int oo = o - 2 * DMODEL;
            const int h = oo >> 6, d = oo & 63;
            float* base = g_V + ((size_t)(b * HEADS + h) * LSEQ << 6) + d;
            #pragma unroll
            for (int j = 0; j < 8; j++)
                base[(size_t)(lbase + j) << 6] = acc[i][j];
        }
    }
}

// ---------------------------------------------------------------------------
// Flash attention, fp32 SIMT, v2: 128x64 (q x k) CTA tile, 8x4 thread tile.
// Raises FMA-per-LDS from 8 to 10.7 in both GEMM loops (L1 was the binding
// pipe at 87.9%). 2 CTAs/SM @ 101 KB smem.
// ---------------------------------------------------------------------------
#define QST 132            // padded stride for q-dim arrays (128 + 4)
#define KST 68             // padded stride for k/d-dim arrays (64 + 4)
#define QTILE 128
#define ATTN_SMEM ((2 * 64 * QST + 2 * 64 * KST + 64 + 256) * (int)sizeof(float))

__global__ __launch_bounds__(256, 2)
void attn_kernel(const int* __restrict__ mask, float* __restrict__ out)
{
    extern __shared__ float sm[];
    float* Qts     = sm;                  // [d][q]  64 x QST
    float* Kts     = Qts + 64 * QST;      // [d][k]  64 x KST
    float* Vs      = Kts + 64 * KST;      // [k][d]  64 x KST
    float* Sts     = Vs  + 64 * KST;      // [k][q]  64 x QST (reused as O[d][q])
    float* maskf   = Sts + 64 * QST;      // [64]
    float* alpha_s = maskf + 64;          // [128]
    float* l_s     = alpha_s + 128;       // [128]

    const int t  = threadIdx.x;
    const int tx = t & 15;               // k group: 4*tx
    const int ty = t >> 4;               // q group: 8*ty
    const int q0 = blockIdx.x * QTILE;
    const int bh = blockIdx.y;
    const int b  = bh >> 4;
    const int h  = bh & 15;

    const float* Qb = g_Q + (size_t)bh * DH * LSEQ;
    const float* Kb = g_K + (size_t)bh * DH * LSEQ;
    const float* Vb = g_V + (size_t)bh * LSEQ * DH;

    // Load Q tile: Qts[d][q] <- Qb[d][q0+q], 64x128 floats = 2048 float4
    #pragma unroll
    for (int r = 0; r < 8; r++) {
        int f = t + r * 256;             // 0..2047
        int row = f >> 5, c = (f & 31) * 4;
        *(float4*)&Qts[row * QST + c] =
            *(const float4*)(Qb + (size_t)row * LSEQ + q0 + c);
    }

    float acc[8][4];
    #pragma unroll
    for (int i = 0; i < 8; i++)
        #pragma unroll
        for (int j = 0; j < 4; j++) acc[i][j] = 0.f;

    float m_run = __int_as_float(0xff800000);  // -inf (q-row t, for t < 128)
    float l_run = 0.f;

    for (int k0 = 0; k0 < LSEQ; k0 += 64) {
        __syncthreads();  // prev-iter consumers done (also publishes Qts on iter 0)

        // Load K tile [d][k] and V tile [k][d]: each 64x64 = 1024 float4
        #pragma unroll
        for (int r = 0; r < 4; r++) {
            int f = t + r * 256;
            int row = f >> 4, c = (f & 15) * 4;
            *(float4*)&Kts[row * KST + c] =
                *(const float4*)(Kb + (size_t)row * LSEQ + k0 + c);
            *(float4*)&Vs[row * KST + c] =
                *(const float4*)(Vb + ((size_t)(k0 + row) << 6) + c);
        }
        if (t < 64) maskf[t] = (float)mask[b * LSEQ + k0 + t];
        __syncthreads();

        // S = Q K^T over dh: thread block (q = 8ty+i, k = 4tx+j)
        float s[8][4];
        #pragma unroll
        for (int i = 0; i < 8; i++)
            #pragma unroll
            for (int j = 0; j < 4; j++) s[i][j] = 0.f;

        #pragma unroll 8
        for (int d = 0; d < 64; d++) {
            float a[8];
            *(float4*)(a)     = *(float4*)&Qts[d * QST + 8 * ty];
            *(float4*)(a + 4) = *(float4*)&Qts[d * QST + 8 * ty + 4];
            float4 kv = *(float4*)&Kts[d * KST + 4 * tx];
            #pragma unroll
            for (int i = 0; i < 8; i++) {
                s[i][0] += a[i] * kv.x;
                s[i][1] += a[i] * kv.y;
                s[i][2] += a[i] * kv.z;
                s[i][3] += a[i] * kv.w;
            }
        }

        // Mask + store S transposed: Sts[k][q]
        #pragma unroll
        for (int j = 0; j < 4; j++) {
            float km = maskf[4 * tx + j];
            float4 sv0, sv1;
            sv0.x = (km > 0.5f) ? s[0][j] : -1e30f;
            sv0.y = (km > 0.5f) ? s[1][j] : -1e30f;
            sv0.z = (km > 0.5f) ? s[2][j] : -1e30f;
            sv0.w = (km > 0.5f) ? s[3][j] : -1e30f;
            sv1.x = (km > 0.5f) ? s[4][j] : -1e30f;
            sv1.y = (km > 0.5f) ? s[5][j] : -1e30f;
            sv1.z = (km > 0.5f) ? s[6][j] : -1e30f;
            sv1.w = (km > 0.5f) ? s[7][j] : -1e30f;
            *(float4*)&Sts[(4 * tx + j) * QST + 8 * ty]     = sv0;
            *(float4*)&Sts[(4 * tx + j) * QST + 8 * ty + 4] = sv1;
        }
        __syncthreads();

        // Online softmax: one thread per q row (t < 128); lane-consecutive reads
        if (t < 128) {
            float tmax = __int_as_float(0xff800000);
            #pragma unroll 8
            for (int k = 0; k < 64; k++)
                tmax = fmaxf(tmax, Sts[k * QST + t]);
            float mn  = fmaxf(m_run, tmax);
            float al  = __expf(m_run - mn);   // 0 on first tile
            float sum = 0.f;
            #pragma unroll 8
            for (int k = 0; k < 64; k++) {
                float p = __expf(Sts[k * QST + t] - mn);
                Sts[k * QST + t] = p;
                sum += p;
            }
            l_run = l_run * al + sum;
            m_run = mn;
            alpha_s[t] = al;
        }
        __syncthreads();

        // Rescale accumulators and add P @ V
        float al_i[8];
        #pragma unroll
        for (int i = 0; i < 8; i++) al_i[i] = alpha_s[8 * ty + i];
        #pragma unroll
        for (int i = 0; i < 8; i++)
            #pragma unroll
            for (int j = 0; j < 4; j++) acc[i][j] *= al_i[i];

        #pragma unroll 8
        for (int k = 0; k < 64; k++) {
            float p[8];
            *(float4*)(p)     = *(float4*)&Sts[k * QST + 8 * ty];
            *(float4*)(p + 4) = *(float4*)&Sts[k * QST + 8 * ty + 4];
            float4 vv = *(float4*)&Vs[k * KST + 4 * tx];
            #pragma unroll
            for (int i = 0; i < 8; i++) {
                acc[i][0] += p[i] * vv.x;
                acc[i][1] += p[i] * vv.y;
                acc[i][2] += p[i] * vv.z;
                acc[i][3] += p[i] * vv.w;
            }
        }
    }

    if (t < 128) l_s[t] = l_run;
    __syncthreads();

    // Normalize and stage transposed output O[d][q] into Sts (64 x 128)
    float inv_i[8];
    #pragma unroll
    for (int i = 0; i < 8; i++) inv_i[i] = 1.f / l_s[8 * ty + i];
    #pragma unroll
    for (int j = 0; j < 4; j++) {
        float4 ov0, ov1;
        ov0.x = acc[0][j] * inv_i[0];
        ov0.y = acc[1][j] * inv_i[1];
        ov0.z = acc[2][j] * inv_i[2];
        ov0.w = acc[3][j] * inv_i[3];
        ov1.x = acc[4][j] * inv_i[4];
        ov1.y = acc[5][j] * inv_i[5];
        ov1.z = acc[6][j] * inv_i[6];
        ov1.w = acc[7][j] * inv_i[7];
        *(float4*)&Sts[(4 * tx + j) * QST + 8 * ty]     = ov0;
        *(float4*)&Sts[(4 * tx + j) * QST + 8 * ty + 4] = ov1;
    }
    __syncthreads();

    // Coalesced write: out[b][h*64+d][q0+q], 64x128 = 2048 float4
    float* ob = out + ((size_t)b * DMODEL + h * DH) * LSEQ;
    #pragma unroll
    for (int r = 0; r < 8; r++) {
        int f = t + r * 256;
        int row = f >> 5, c = (f & 31) * 4;
        *(float4*)(ob + (size_t)row * LSEQ + q0 + c) =
            *(float4*)&Sts[row * QST + c];
    }
}

// ---------------------------------------------------------------------------
extern "C" void kernel_launch(void* const* d_in, const int* in_sizes, int n_in,
                              void* d_out, int out_size)
{
    const float* x    = (const float*)d_in[0];
    const float* Wq   = (const float*)d_in[1];
    const float* Wkv  = (const float*)d_in[2];
    const int*   mask = (const int*)d_in[3];
    float* out = (float*)d_out;

    cudaFuncSetAttribute(attn_kernel,
                         cudaFuncAttributeMaxDynamicSharedMemorySize, ATTN_SMEM);

    proj_kernel<<<dim3(LSEQ / PBN, (3 * DMODEL) / PBM, BATCH), 256>>>(x, Wq, Wkv);
    attn_kernel<<<dim3(LSEQ / QTILE, BATCH * HEADS), 256, ATTN_SMEM>>>(mask, out);
}

// round 12
// speedup vs baseline: 1.4627x; 1.3939x over previous
#include <cuda_runtime.h>
#include <math.h>

#define BATCH  4
#define DMODEL 1024
#define LSEQ   2048
#define HEADS  16
#define DH     64

// Scratch: Q,K in [B][H][dh][L] (L contiguous), V in [B][H][L][dh] (dh contiguous)
__device__ float g_Q[(size_t)BATCH * HEADS * DH * LSEQ];
__device__ float g_K[(size_t)BATCH * HEADS * DH * LSEQ];
__device__ float g_V[(size_t)BATCH * HEADS * LSEQ * DH];

// ---------------------------------------------------------------------------
// tf32 helpers
// ---------------------------------------------------------------------------
__device__ __forceinline__ unsigned f2tf32(float f) {
    unsigned u;
    asm("cvt.rna.tf32.f32 %0, %1;" : "=r"(u) : "f"(f));
    return u;
}

__device__ __forceinline__ void mma_tf32(float c[4],
                                         unsigned a0, unsigned a1, unsigned a2, unsigned a3,
                                         unsigned b0, unsigned b1) {
    asm volatile(
        "mma.sync.aligned.m16n8k8.row.col.f32.tf32.tf32.f32 "
        "{%0,%1,%2,%3}, {%4,%5,%6,%7}, {%8,%9}, {%0,%1,%2,%3};"
        : "+f"(c[0]), "+f"(c[1]), "+f"(c[2]), "+f"(c[3])
        : "r"(a0), "r"(a1), "r"(a2), "r"(a3), "r"(b0), "r"(b1));
}

// ---------------------------------------------------------------------------
// QKV projection, tf32 tensor-core version.
// out[o, l] = sum_d W[o,d] * x[b,d,l];  o block of 128 is entirely Q, K or V.
// CTA: 128(o) x 128(l), k-chunk 32. 8 warps in 2(o) x 4(l) grid,
// warp tile 64x32 = 4 m-frags x 4 n-frags of m16n8k8.
// smem A=[k][o], B=[k][l], stride 136 -> bank = (8k + col) % 32, conflict-free
// fragment loads.
// ---------------------------------------------------------------------------
#define KB   32
#define SAST 136

__global__ __launch_bounds__(256, 2)
void proj_kernel(const float* __restrict__ x, const float* __restrict__ Wq,
                 const float* __restrict__ Wkv)
{
    __shared__ float As[KB * SAST];   // [k][o] tf32 bit patterns
    __shared__ float Bs[KB * SAST];   // [k][l]

    const int b  = blockIdx.z;
    const int o0 = blockIdx.y * 128;
    const int l0 = blockIdx.x * 128;
    const int t  = threadIdx.x;
    const int lane = t & 31;
    const int wid  = t >> 5;
    const int ow = (wid & 1) * 64;    // warp o-offset in tile
    const int lw = (wid >> 1) * 32;   // warp l-offset in tile

    const float* Wbase = (o0 < DMODEL) ? (Wq + (size_t)o0 * DMODEL)
                                       : (Wkv + (size_t)(o0 - DMODEL) * DMODEL);
    const float* xb = x + (size_t)b * DMODEL * LSEQ;

    const int wrow = t >> 1;          // 0..127: o row this thread stages
    const int wh   = t & 1;           // k half: 0 -> k 0..15, 1 -> k 16..31

    float c[4][4][4];
    #pragma unroll
    for (int i = 0; i < 4; i++)
        #pragma unroll
        for (int j = 0; j < 4; j++)
            #pragma unroll
            for (int r = 0; r < 4; r++) c[i][j][r] = 0.f;

    for (int kb = 0; kb < DMODEL; kb += KB) {
        __syncthreads();  // previous-iteration consumers done

        // Stage W tile -> As[k][o] (tf32)
        {
            const float4* wp = (const float4*)(Wbase + (size_t)wrow * DMODEL + kb + wh * 16);
            #pragma unroll
            for (int r = 0; r < 4; r++) {
                float4 v = wp[r];
                int k = wh * 16 + r * 4;
                As[(k + 0) * SAST + wrow] = __uint_as_float(f2tf32(v.x));
                As[(k + 1) * SAST + wrow] = __uint_as_float(f2tf32(v.y));
                As[(k + 2) * SAST + wrow] = __uint_as_float(f2tf32(v.z));
                As[(k + 3) * SAST + wrow] = __uint_as_float(f2tf32(v.w));
            }
        }
        // Stage x tile -> Bs[k][l] (tf32)
        #pragma unroll
        for (int r = 0; r < 4; r++) {
            int f = t + r * 256;
            int krow = f >> 5, cc = (f & 31) * 4;
            float4 v = *(const float4*)(xb + (size_t)(kb + krow) * LSEQ + l0 + cc);
            uint4 tv = make_uint4(f2tf32(v.x), f2tf32(v.y), f2tf32(v.z), f2tf32(v.w));
            *(uint4*)&Bs[krow * SAST + cc] = tv;
        }
        __syncthreads();

        // 4 k8-steps of mma
        #pragma unroll
        for (int ks = 0; ks < 4; ks++) {
            const int k0 = ks * 8 + (lane & 3);
            unsigned a[4][4];
            #pragma unroll
            for (int i = 0; i < 4; i++) {
                int oA = ow + 16 * i + (lane >> 2);
                a[i][0] = __float_as_uint(As[(k0    ) * SAST + oA    ]);
                a[i][1] = __float_as_uint(As[(k0    ) * SAST + oA + 8]);
                a[i][2] = __float_as_uint(As[(k0 + 4) * SAST + oA    ]);
                a[i][3] = __float_as_uint(As[(k0 + 4) * SAST + oA + 8]);
            }
            unsigned bb[4][2];
            #pragma unroll
            for (int j = 0; j < 4; j++) {
                int lB = lw + 8 * j + (lane >> 2);
                bb[j][0] = __float_as_uint(Bs[(k0    ) * SAST + lB]);
                bb[j][1] = __float_as_uint(Bs[(k0 + 4) * SAST + lB]);
            }
            #pragma unroll
            for (int i = 0; i < 4; i++)
                #pragma unroll
                for (int j = 0; j < 4; j++)
                    mma_tf32(c[i][j], a[i][0], a[i][1], a[i][2], a[i][3],
                             bb[j][0], bb[j][1]);
        }
    }

    // Epilogue. C frag element (row, col): c0,c1 at row=lane>>2, col=2*(lane&3)+{0,1};
    // c2,c3 at row+8. o = o0+ow+16i+row; l = l0+lw+8j+col.
    const int r0  = lane >> 2;
    const int cl0 = 2 * (lane & 3);
    const bool isQ = (o0 < DMODEL);
    const bool isV = (o0 >= 2 * DMODEL);
    const float scale = isQ ? 0.125f : 1.f;
    const int om_base = o0 - (isQ ? 0 : (isV ? 2 * DMODEL : DMODEL));

    if (!isV) {
        float* dst = (isQ ? g_Q : g_K) + (size_t)b * DMODEL * LSEQ;
        #pragma unroll
        for (int i = 0; i < 4; i++) {
            #pragma unroll
            for (int half = 0; half < 2; half++) {
                int om = om_base + ow + 16 * i + r0 + 8 * half;
                float* rowp = dst + (size_t)om * LSEQ + l0 + lw + cl0;
                #pragma unroll
                for (int j = 0; j < 4; j++) {
                    float2 v = make_float2(c[i][j][2 * half] * scale,
                                           c[i][j][2 * half + 1] * scale);
                    *(float2*)&rowp[8 * j] = v;
                }
            }
        }
    } else {
        float* vdst = g_V + (size_t)b * DMODEL * LSEQ;
        #pragma unroll
        for (int i = 0; i < 4; i++) {
            #pragma unroll
            for (int half = 0; half < 2; half++) {
                int om = om_base + ow + 16 * i + r0 + 8 * half;
                int h = om >> 6, d = om & 63;
                float* basep = vdst + (size_t)h * LSEQ * DH + d;
                #pragma unroll
                for (int j = 0; j < 4; j++) {
                    int l = l0 + lw + 8 * j + cl0;
                    basep[(size_t)l * DH]       = c[i][j][2 * half];
                    basep[(size_t)(l + 1) * DH] = c[i][j][2 * half + 1];
                }
            }
        }
    }
}

// ---------------------------------------------------------------------------
// Flash attention, fp32 SIMT v2 (unchanged from round-10 passing kernel):
// 128x64 (q x k) CTA tile, 8x4 thread tile, 2 CTAs/SM.
// ---------------------------------------------------------------------------
#define QST 132
#define KST 68
#define QTILE 128
#define ATTN_SMEM ((2 * 64 * QST + 2 * 64 * KST + 64 + 256) * (int)sizeof(float))

__global__ __launch_bounds__(256, 2)
void attn_kernel(const int* __restrict__ mask, float* __restrict__ out)
{
    extern __shared__ float sm[];
    float* Qts     = sm;                  // [d][q]  64 x QST
    float* Kts     = Qts + 64 * QST;      // [d][k]  64 x KST
    float* Vs      = Kts + 64 * KST;      // [k][d]  64 x KST
    float* Sts     = Vs  + 64 * KST;      // [k][q]  64 x QST (reused as O[d][q])
    float* maskf   = Sts + 64 * QST;      // [64]
    float* alpha_s = maskf + 64;          // [128]
    float* l_s     = alpha_s + 128;       // [128]

    const int t  = threadIdx.x;
    const int tx = t & 15;
    const int ty = t >> 4;
    const int q0 = blockIdx.x * QTILE;
    const int bh = blockIdx.y;
    const int b  = bh >> 4;
    const int h  = bh & 15;

    const float* Qb = g_Q + (size_t)bh * DH * LSEQ;
    const float* Kb = g_K + (size_t)bh * DH * LSEQ;
    const float* Vb = g_V + (size_t)bh * LSEQ * DH;

    #pragma unroll
    for (int r = 0; r < 8; r++) {
        int f = t + r * 256;
        int row = f >> 5, c = (f & 31) * 4;
        *(float4*)&Qts[row * QST + c] =
            *(const float4*)(Qb + (size_t)row * LSEQ + q0 + c);
    }

    float acc[8][4];
    #pragma unroll
    for (int i = 0; i < 8; i++)
        #pragma unroll
        for (int j = 0; j < 4; j++) acc[i][j] = 0.f;

    float m_run = __int_as_float(0xff800000);
    float l_run = 0.f;

    for (int k0 = 0; k0 < LSEQ; k0 += 64) {
        __syncthreads();

        #pragma unroll
        for (int r = 0; r < 4; r++) {
            int f = t + r * 256;
            int row = f >> 4, c = (f & 15) * 4;
            *(float4*)&Kts[row * KST + c] =
                *(const float4*)(Kb + (size_t)row * LSEQ + k0 + c);
            *(float4*)&Vs[row * KST + c] =
                *(const float4*)(Vb + ((size_t)(k0 + row) << 6) + c);
        }
        if (t < 64) maskf[t] = (float)mask[b * LSEQ + k0 + t];
        __syncthreads();

        float s[8][4];
        #pragma unroll
        for (int i = 0; i < 8; i++)
            #pragma unroll
            for (int j = 0; j < 4; j++) s[i][j] = 0.f;

        #pragma unroll 8
        for (int d = 0; d < 64; d++) {
            float a[8];
            *(float4*)(a)     = *(float4*)&Qts[d * QST + 8 * ty];
            *(float4*)(a + 4) = *(float4*)&Qts[d * QST + 8 * ty + 4];
            float4 kv = *(float4*)&Kts[d * KST + 4 * tx];
            #pragma unroll
            for (int i = 0; i < 8; i++) {
                s[i][0] += a[i] * kv.x;
                s[i][1] += a[i] * kv.y;
                s[i][2] += a[i] * kv.z;
                s[i][3] += a[i] * kv.w;
            }
        }

        #pragma unroll
        for (int j = 0; j < 4; j++) {
            float km = maskf[4 * tx + j];
            float4 sv0, sv1;
            sv0.x = (km > 0.5f) ? s[0][j] : -1e30f;
            sv0.y = (km > 0.5f) ? s[1][j] : -1e30f;
            sv0.z = (km > 0.5f) ? s[2][j] : -1e30f;
            sv0.w = (km > 0.5f) ? s[3][j] : -1e30f;
            sv1.x = (km > 0.5f) ? s[4][j] : -1e30f;
            sv1.y = (km > 0.5f) ? s[5][j] : -1e30f;
            sv1.z = (km > 0.5f) ? s[6][j] : -1e30f;
            sv1.w = (km > 0.5f) ? s[7][j] : -1e30f;
            *(float4*)&Sts[(4 * tx + j) * QST + 8 * ty]     = sv0;
            *(float4*)&Sts[(4 * tx + j) * QST + 8 * ty + 4] = sv1;
        }
        __syncthreads();

        if (t < 128) {
            float tmax = __int_as_float(0xff800000);
            #pragma unroll 8
            for (int k = 0; k < 64; k++)
                tmax = fmaxf(tmax, Sts[k * QST + t]);
            float mn  = fmaxf(m_run, tmax);
            float al  = __expf(m_run - mn);
            float sum = 0.f;
            #pragma unroll 8
            for (int k = 0; k < 64; k++) {
                float p = __expf(Sts[k * QST + t] - mn);
                Sts[k * QST + t] = p;
                sum += p;
            }
            l_run = l_run * al + sum;
            m_run = mn;
            alpha_s[t] = al;
        }
        __syncthreads();

        float al_i[8];
        #pragma unroll
        for (int i = 0; i < 8; i++) al_i[i] = alpha_s[8 * ty + i];
        #pragma unroll
        for (int i = 0; i < 8; i++)
            #pragma unroll
            for (int j = 0; j < 4; j++) acc[i][j] *= al_i[i];

        #pragma unroll 8
        for (int k = 0; k < 64; k++) {
            float p[8];
            *(float4*)(p)     = *(float4*)&Sts[k * QST + 8 * ty];
            *(float4*)(p + 4) = *(float4*)&Sts[k * QST + 8 * ty + 4];
            float4 vv = *(float4*)&Vs[k * KST + 4 * tx];
            #pragma unroll
            for (int i = 0; i < 8; i++) {
                acc[i][0] += p[i] * vv.x;
                acc[i][1] += p[i] * vv.y;
                acc[i][2] += p[i] * vv.z;
                acc[i][3] += p[i] * vv.w;
            }
        }
    }

    if (t < 128) l_s[t] = l_run;
    __syncthreads();

    float inv_i[8];
    #pragma unroll
    for (int i = 0; i < 8; i++) inv_i[i] = 1.f / l_s[8 * ty + i];
    #pragma unroll
    for (int j = 0; j < 4; j++) {
        float4 ov0, ov1;
        ov0.x = acc[0][j] * inv_i[0];
        ov0.y = acc[1][j] * inv_i[1];
        ov0.z = acc[2][j] * inv_i[2];
        ov0.w = acc[3][j] * inv_i[3];
        ov1.x = acc[4][j] * inv_i[4];
        ov1.y = acc[5][j] * inv_i[5];
        ov1.z = acc[6][j] * inv_i[6];
        ov1.w = acc[7][j] * inv_i[7];
        *(float4*)&Sts[(4 * tx + j) * QST + 8 * ty]     = ov0;
        *(float4*)&Sts[(4 * tx + j) * QST + 8 * ty + 4] = ov1;
    }
    __syncthreads();

    float* ob = out + ((size_t)b * DMODEL + h * DH) * LSEQ;
    #pragma unroll
    for (int r = 0; r < 8; r++) {
        int f = t + r * 256;
        int row = f >> 5, c = (f & 31) * 4;
        *(float4*)(ob + (size_t)row * LSEQ + q0 + c) =
            *(float4*)&Sts[row * QST + c];
    }
}

// ---------------------------------------------------------------------------
extern "C" void kernel_launch(void* const* d_in, const int* in_sizes, int n_in,
                              void* d_out, int out_size)
{
    const float* x    = (const float*)d_in[0];
    const float* Wq   = (const float*)d_in[1];
    const float* Wkv  = (const float*)d_in[2];
    const int*   mask = (const int*)d_in[3];
    float* out = (float*)d_out;

    cudaFuncSetAttribute(attn_kernel,
                         cudaFuncAttributeMaxDynamicSharedMemorySize, ATTN_SMEM);

    proj_kernel<<<dim3(LSEQ / 128, (3 * DMODEL) / 128, BATCH), 256>>>(x, Wq, Wkv);
    attn_kernel<<<dim3(LSEQ / QTILE, BATCH * HEADS), 256, ATTN_SMEM>>>(mask, out);
}

// round 13
// speedup vs baseline: 2.1722x; 1.4850x over previous
#include <cuda_runtime.h>
#include <math.h>

#define BATCH  4
#define DMODEL 1024
#define LSEQ   2048
#define HEADS  16
#define DH     64

__device__ float g_Q[(size_t)BATCH * HEADS * DH * LSEQ];
__device__ float g_K[(size_t)BATCH * HEADS * DH * LSEQ];
__device__ float g_V[(size_t)BATCH * HEADS * LSEQ * DH];

// ---------------------------------------------------------------------------
// tf32 helpers (fragment mappings HW-validated by round-12 proj kernel)
// ---------------------------------------------------------------------------
__device__ __forceinline__ unsigned f2tf32(float f) {
    unsigned u;
    asm("cvt.rna.tf32.f32 %0, %1;" : "=r"(u) : "f"(f));
    return u;
}

__device__ __forceinline__ void mma_tf32(float c[4],
                                         unsigned a0, unsigned a1, unsigned a2, unsigned a3,
                                         unsigned b0, unsigned b1) {
    asm volatile(
        "mma.sync.aligned.m16n8k8.row.col.f32.tf32.tf32.f32 "
        "{%0,%1,%2,%3}, {%4,%5,%6,%7}, {%8,%9}, {%0,%1,%2,%3};"
        : "+f"(c[0]), "+f"(c[1]), "+f"(c[2]), "+f"(c[3])
        : "r"(a0), "r"(a1), "r"(a2), "r"(a3), "r"(b0), "r"(b1));
}

// split a into tf32 hi + lo (a ≈ hi + lo, each exactly representable in tf32)
__device__ __forceinline__ void tf32_split(float a, unsigned& hi, unsigned& lo) {
    hi = f2tf32(a);
    lo = f2tf32(a - __uint_as_float(hi));
}

// ---------------------------------------------------------------------------
// QKV projection, tf32 tensor-core (unchanged from round-12 passing kernel)
// ---------------------------------------------------------------------------
#define KB   32
#define SAST 136

__global__ __launch_bounds__(256, 2)
void proj_kernel(const float* __restrict__ x, const float* __restrict__ Wq,
                 const float* __restrict__ Wkv)
{
    __shared__ float As[KB * SAST];
    __shared__ float Bs[KB * SAST];

    const int b  = blockIdx.z;
    const int o0 = blockIdx.y * 128;
    const int l0 = blockIdx.x * 128;
    const int t  = threadIdx.x;
    const int lane = t & 31;
    const int wid  = t >> 5;
    const int ow = (wid & 1) * 64;
    const int lw = (wid >> 1) * 32;

    const float* Wbase = (o0 < DMODEL) ? (Wq + (size_t)o0 * DMODEL)
                                       : (Wkv + (size_t)(o0 - DMODEL) * DMODEL);
    const float* xb = x + (size_t)b * DMODEL * LSEQ;

    const int wrow = t >> 1;
    const int wh   = t & 1;

    float c[4][4][4];
    #pragma unroll
    for (int i = 0; i < 4; i++)
        #pragma unroll
        for (int j = 0; j < 4; j++)
            #pragma unroll
            for (int r = 0; r < 4; r++) c[i][j][r] = 0.f;

    for (int kb = 0; kb < DMODEL; kb += KB) {
        __syncthreads();

        {
            const float4* wp = (const float4*)(Wbase + (size_t)wrow * DMODEL + kb + wh * 16);
            #pragma unroll
            for (int r = 0; r < 4; r++) {
                float4 v = wp[r];
                int k = wh * 16 + r * 4;
                As[(k + 0) * SAST + wrow] = __uint_as_float(f2tf32(v.x));
                As[(k + 1) * SAST + wrow] = __uint_as_float(f2tf32(v.y));
                As[(k + 2) * SAST + wrow] = __uint_as_float(f2tf32(v.z));
                As[(k + 3) * SAST + wrow] = __uint_as_float(f2tf32(v.w));
            }
        }
        #pragma unroll
        for (int r = 0; r < 4; r++) {
            int f = t + r * 256;
            int krow = f >> 5, cc = (f & 31) * 4;
            float4 v = *(const float4*)(xb + (size_t)(kb + krow) * LSEQ + l0 + cc);
            uint4 tv = make_uint4(f2tf32(v.x), f2tf32(v.y), f2tf32(v.z), f2tf32(v.w));
            *(uint4*)&Bs[krow * SAST + cc] = tv;
        }
        __syncthreads();

        #pragma unroll
        for (int ks = 0; ks < 4; ks++) {
            const int k0 = ks * 8 + (lane & 3);
            unsigned a[4][4];
            #pragma unroll
            for (int i = 0; i < 4; i++) {
                int oA = ow + 16 * i + (lane >> 2);
                a[i][0] = __float_as_uint(As[(k0    ) * SAST + oA    ]);
                a[i][1] = __float_as_uint(As[(k0    ) * SAST + oA + 8]);
                a[i][2] = __float_as_uint(As[(k0 + 4) * SAST + oA    ]);
                a[i][3] = __float_as_uint(As[(k0 + 4) * SAST + oA + 8]);
            }
            unsigned bb[4][2];
            #pragma unroll
            for (int j = 0; j < 4; j++) {
                int lB = lw + 8 * j + (lane >> 2);
                bb[j][0] = __float_as_uint(Bs[(k0    ) * SAST + lB]);
                bb[j][1] = __float_as_uint(Bs[(k0 + 4) * SAST + lB]);
            }
            #pragma unroll
            for (int i = 0; i < 4; i++)
                #pragma unroll
                for (int j = 0; j < 4; j++)
                    mma_tf32(c[i][j], a[i][0], a[i][1], a[i][2], a[i][3],
                             bb[j][0], bb[j][1]);
        }
    }

    const int r0  = lane >> 2;
    const int cl0 = 2 * (lane & 3);
    const bool isQ = (o0 < DMODEL);
    const bool isV = (o0 >= 2 * DMODEL);
    const float scale = isQ ? 0.125f : 1.f;
    const int om_base = o0 - (isQ ? 0 : (isV ? 2 * DMODEL : DMODEL));

    if (!isV) {
        float* dst = (isQ ? g_Q : g_K) + (size_t)b * DMODEL * LSEQ;
        #pragma unroll
        for (int i = 0; i < 4; i++) {
            #pragma unroll
            for (int half = 0; half < 2; half++) {
                int om = om_base + ow + 16 * i + r0 + 8 * half;
                float* rowp = dst + (size_t)om * LSEQ + l0 + lw + cl0;
                #pragma unroll
                for (int j = 0; j < 4; j++) {
                    float2 v = make_float2(c[i][j][2 * half] * scale,
                                           c[i][j][2 * half + 1] * scale);
                    *(float2*)&rowp[8 * j] = v;
                }
            }
        }
    } else {
        float* vdst = g_V + (size_t)b * DMODEL * LSEQ;
        #pragma unroll
        for (int i = 0; i < 4; i++) {
            #pragma unroll
            for (int half = 0; half < 2; half++) {
                int om = om_base + ow + 16 * i + r0 + 8 * half;
                int h = om >> 6, d = om & 63;
                float* basep = vdst + (size_t)h * LSEQ * DH + d;
                #pragma unroll
                for (int j = 0; j < 4; j++) {
                    int l = l0 + lw + 8 * j + cl0;
                    basep[(size_t)l * DH]       = c[i][j][2 * half];
                    basep[(size_t)(l + 1) * DH] = c[i][j][2 * half + 1];
                }
            }
        }
    }
}

// ---------------------------------------------------------------------------
// Flash attention v3: tensor-core GEMMs.
// CTA 128(q) x 64(k) tile; 8 warps as 4(q) x 2(k/d), warp tile 32x32
// = 2 m-frags x 4 n-frags of m16n8k8.
// QK^T: tf32x2 split (fp32-accurate logits). PV: plain tf32 (P in [0,1]).
// Softmax/mask/layout identical to round-12 kernel.
// Strides: QST=136, KST=72 -> fragment LDS bank = 8*k + col, conflict-free.
// ---------------------------------------------------------------------------
#define QST 136
#define KST 72
#define QTILE 128
#define ATTN_SMEM ((2 * 64 * QST + 2 * 64 * KST + 64 + 256) * (int)sizeof(float))

__global__ __launch_bounds__(256, 2)
void attn_kernel(const int* __restrict__ mask, float* __restrict__ out)
{
    extern __shared__ float sm[];
    float* Qts     = sm;                  // [d][q]  64 x QST
    float* Kts     = Qts + 64 * QST;      // [d][k]  64 x KST
    float* Vs      = Kts + 64 * KST;      // [k][d]  64 x KST
    float* Sts     = Vs  + 64 * KST;      // [k][q]  64 x QST (P, then O[d][q])
    float* maskf   = Sts + 64 * QST;      // [64]
    float* alpha_s = maskf + 64;          // [128]
    float* l_s     = alpha_s + 128;       // [128]

    const int t    = threadIdx.x;
    const int lane = t & 31;
    const int wid  = t >> 5;
    const int gid  = lane >> 2;           // 0..7
    const int tig  = lane & 3;            // 0..3
    const int qw   = (wid & 3) * 32;      // warp q offset
    const int kdw  = (wid >> 2) * 32;     // warp k offset (QK^T) / d offset (PV)
    const int q0 = blockIdx.x * QTILE;
    const int bh = blockIdx.y;
    const int b  = bh >> 4;
    const int h  = bh & 15;

    const float* Qb = g_Q + (size_t)bh * DH * LSEQ;
    const float* Kb = g_K + (size_t)bh * DH * LSEQ;
    const float* Vb = g_V + (size_t)bh * LSEQ * DH;

    // Load Q tile: Qts[d][q]
    #pragma unroll
    for (int r = 0; r < 8; r++) {
        int f = t + r * 256;
        int row = f >> 5, c = (f & 31) * 4;
        *(float4*)&Qts[row * QST + c] =
            *(const float4*)(Qb + (size_t)row * LSEQ + q0 + c);
    }

    float oacc[2][4][4];
    #pragma unroll
    for (int mi = 0; mi < 2; mi++)
        #pragma unroll
        for (int nj = 0; nj < 4; nj++)
            #pragma unroll
            for (int r = 0; r < 4; r++) oacc[mi][nj][r] = 0.f;

    float m_run = __int_as_float(0xff800000);
    float l_run = 0.f;

    for (int k0 = 0; k0 < LSEQ; k0 += 64) {
        __syncthreads();  // prev-iter PV reads of Sts / K,V consumers done

        #pragma unroll
        for (int r = 0; r < 4; r++) {
            int f = t + r * 256;
            int row = f >> 4, c = (f & 15) * 4;
            *(float4*)&Kts[row * KST + c] =
                *(const float4*)(Kb + (size_t)row * LSEQ + k0 + c);
            *(float4*)&Vs[row * KST + c] =
                *(const float4*)(Vb + ((size_t)(k0 + row) << 6) + c);
        }
        if (t < 64) maskf[t] = (float)mask[b * LSEQ + k0 + t];
        __syncthreads();

        // ---- S = Q K^T  (tf32x2: hi*hi + hi*lo + lo*hi) ----
        float sC[2][4][4];
        #pragma unroll
        for (int mi = 0; mi < 2; mi++)
            #pragma unroll
            for (int nj = 0; nj < 4; nj++)
                #pragma unroll
                for (int r = 0; r < 4; r++) sC[mi][nj][r] = 0.f;

        #pragma unroll
        for (int ks = 0; ks < 8; ks++) {
            const int dA = ks * 8 + tig;
            unsigned ahi[2][4], alo[2][4];
            #pragma unroll
            for (int mi = 0; mi < 2; mi++) {
                int qa = qw + 16 * mi + gid;
                tf32_split(Qts[dA * QST + qa],           ahi[mi][0], alo[mi][0]);
                tf32_split(Qts[dA * QST + qa + 8],       ahi[mi][1], alo[mi][1]);
                tf32_split(Qts[(dA + 4) * QST + qa],     ahi[mi][2], alo[mi][2]);
                tf32_split(Qts[(dA + 4) * QST + qa + 8], ahi[mi][3], alo[mi][3]);
            }
            #pragma unroll
            for (int nj = 0; nj < 4; nj++) {
                int kc = kdw + 8 * nj + gid;
                unsigned b0h, b0l, b1h, b1l;
                tf32_split(Kts[dA * KST + kc],       b0h, b0l);
                tf32_split(Kts[(dA + 4) * KST + kc], b1h, b1l);
                #pragma unroll
                for (int mi = 0; mi < 2; mi++) {
                    mma_tf32(sC[mi][nj], ahi[mi][0], ahi[mi][1], ahi[mi][2], ahi[mi][3], b0h, b1h);
                    mma_tf32(sC[mi][nj], ahi[mi][0], ahi[mi][1], ahi[mi][2], ahi[mi][3], b0l, b1l);
                    mma_tf32(sC[mi][nj], alo[mi][0], alo[mi][1], alo[mi][2], alo[mi][3], b0h, b1h);
                }
            }
        }

        // ---- mask + store S transposed: Sts[k][q] ----
        #pragma unroll
        for (int mi = 0; mi < 2; mi++) {
            int qa = qw + 16 * mi + gid;
            #pragma unroll
            for (int nj = 0; nj < 4; nj++) {
                int kc = kdw + 8 * nj + 2 * tig;
                float km0 = maskf[kc], km1 = maskf[kc + 1];
                Sts[kc * QST + qa]           = (km0 > 0.5f) ? sC[mi][nj][0] : -1e30f;
                Sts[(kc + 1) * QST + qa]     = (km1 > 0.5f) ? sC[mi][nj][1] : -1e30f;
                Sts[kc * QST + qa + 8]       = (km0 > 0.5f) ? sC[mi][nj][2] : -1e30f;
                Sts[(kc + 1) * QST + qa + 8] = (km1 > 0.5f) ? sC[mi][nj][3] : -1e30f;
            }
        }
        __syncthreads();

        // ---- online softmax (one thread per q row) ----
        if (t < 128) {
            float tmax = __int_as_float(0xff800000);
            #pragma unroll 8
            for (int k = 0; k < 64; k++)
                tmax = fmaxf(tmax, Sts[k * QST + t]);
            float mn  = fmaxf(m_run, tmax);
            float al  = __expf(m_run - mn);
            float sum = 0.f;
            #pragma unroll 8
            for (int k = 0; k < 64; k++) {
                float p = __expf(Sts[k * QST + t] - mn);
                Sts[k * QST + t] = p;
                sum += p;
            }
            l_run = l_run * al + sum;
            m_run = mn;
            alpha_s[t] = al;
        }
        __syncthreads();

        // ---- rescale O, then O += P @ V (tf32) ----
        #pragma unroll
        for (int mi = 0; mi < 2; mi++) {
            int qa = qw + 16 * mi + gid;
            float al0 = alpha_s[qa], al1 = alpha_s[qa + 8];
            #pragma unroll
            for (int nj = 0; nj < 4; nj++) {
                oacc[mi][nj][0] *= al0;
                oacc[mi][nj][1] *= al0;
                oacc[mi][nj][2] *= al1;
                oacc[mi][nj][3] *= al1;
            }
        }

        #pragma unroll
        for (int ks = 0; ks < 8; ks++) {
            const int kA = ks * 8 + tig;
            unsigned pa[2][4];
            #pragma unroll
            for (int mi = 0; mi < 2; mi++) {
                int qa = qw + 16 * mi + gid;
                pa[mi][0] = f2tf32(Sts[kA * QST + qa]);
                pa[mi][1] = f2tf32(Sts[kA * QST + qa + 8]);
                pa[mi][2] = f2tf32(Sts[(kA + 4) * QST + qa]);
                pa[mi][3] = f2tf32(Sts[(kA + 4) * QST + qa + 8]);
            }
            #pragma unroll
            for (int nj = 0; nj < 4; nj++) {
                int dc = kdw + 8 * nj + gid;
                unsigned v0 = f2tf32(Vs[kA * KST + dc]);
                unsigned v1 = f2tf32(Vs[(kA + 4) * KST + dc]);
                #pragma unroll
                for (int mi = 0; mi < 2; mi++)
                    mma_tf32(oacc[mi][nj], pa[mi][0], pa[mi][1], pa[mi][2], pa[mi][3], v0, v1);
            }
        }
    }

    if (t < 128) l_s[t] = l_run;
    __syncthreads();  // also protects Sts (last PV reads) before O overwrite

    // ---- normalize, stage O[d][q] into Sts ----
    #pragma unroll
    for (int mi = 0; mi < 2; mi++) {
        int qa = qw + 16 * mi + gid;
        float inv0 = 1.f / l_s[qa];
        float inv1 = 1.f / l_s[qa + 8];
        #pragma unroll
        for (int nj = 0; nj < 4; nj++) {
            int dc = kdw + 8 * nj + 2 * tig;
            Sts[dc * QST + qa]           = oacc[mi][nj][0] * inv0;
            Sts[(dc + 1) * QST + qa]     = oacc[mi][nj][1] * inv0;
            Sts[dc * QST + qa + 8]       = oacc[mi][nj][2] * inv1;
            Sts[(dc + 1) * QST + qa + 8] = oacc[mi][nj][3] * inv1;
        }
    }
    __syncthreads();

    // ---- coalesced write: out[b][h*64+d][q0+q] ----
    float* ob = out + ((size_t)b * DMODEL + h * DH) * LSEQ;
    #pragma unroll
    for (int r = 0; r < 8; r++) {
        int f = t + r * 256;
        int row = f >> 5, c = (f & 31) * 4;
        *(float4*)(ob + (size_t)row * LSEQ + q0 + c) =
            *(float4*)&Sts[row * QST + c];
    }
}

// ---------------------------------------------------------------------------
extern "C" void kernel_launch(void* const* d_in, const int* in_sizes, int n_in,
                              void* d_out, int out_size)
{
    const float* x    = (const float*)d_in[0];
    const float* Wq   = (const float*)d_in[1];
    const float* Wkv  = (const float*)d_in[2];
    const int*   mask = (const int*)d_in[3];
    float* out = (float*)d_out;

    cudaFuncSetAttribute(attn_kernel,
                         cudaFuncAttributeMaxDynamicSharedMemorySize, ATTN_SMEM);

    proj_kernel<<<dim3(LSEQ / 128, (3 * DMODEL) / 128, BATCH), 256>>>(x, Wq, Wkv);
    attn_kernel<<<dim3(LSEQ / QTILE, BATCH * HEADS), 256, ATTN_SMEM>>>(mask, out);
}

// round 15
// speedup vs baseline: 2.2197x; 1.0219x over previous
#include <cuda_runtime.h>
#include <math.h>

#define BATCH  4
#define DMODEL 1024
#define LSEQ   2048
#define HEADS  16
#define DH     64

__device__ float g_Q[(size_t)BATCH * HEADS * DH * LSEQ];
__device__ float g_K[(size_t)BATCH * HEADS * DH * LSEQ];
__device__ float g_V[(size_t)BATCH * HEADS * LSEQ * DH];

// ---------------------------------------------------------------------------
// tf32 helpers (fragment mappings HW-validated in rounds 12/13)
// ---------------------------------------------------------------------------
__device__ __forceinline__ unsigned f2tf32(float f) {
    unsigned u;
    asm("cvt.rna.tf32.f32 %0, %1;" : "=r"(u) : "f"(f));
    return u;
}

__device__ __forceinline__ void mma_tf32(float c[4],
                                         unsigned a0, unsigned a1, unsigned a2, unsigned a3,
                                         unsigned b0, unsigned b1) {
    asm volatile(
        "mma.sync.aligned.m16n8k8.row.col.f32.tf32.tf32.f32 "
        "{%0,%1,%2,%3}, {%4,%5,%6,%7}, {%8,%9}, {%0,%1,%2,%3};"
        : "+f"(c[0]), "+f"(c[1]), "+f"(c[2]), "+f"(c[3])
        : "r"(a0), "r"(a1), "r"(a2), "r"(a3), "r"(b0), "r"(b1));
}

__device__ __forceinline__ void tf32_split(float a, unsigned& hi, unsigned& lo) {
    hi = f2tf32(a);
    lo = f2tf32(a - __uint_as_float(hi));
}

// ---------------------------------------------------------------------------
// QKV projection, tf32 tensor-core (unchanged from round-12/13 passing kernel)
// ---------------------------------------------------------------------------
#define KB   32
#define SAST 136

__global__ __launch_bounds__(256, 2)
void proj_kernel(const float* __restrict__ x, const float* __restrict__ Wq,
                 const float* __restrict__ Wkv)
{
    __shared__ float As[KB * SAST];
    __shared__ float Bs[KB * SAST];

    const int b  = blockIdx.z;
    const int o0 = blockIdx.y * 128;
    const int l0 = blockIdx.x * 128;
    const int t  = threadIdx.x;
    const int lane = t & 31;
    const int wid  = t >> 5;
    const int ow = (wid & 1) * 64;
    const int lw = (wid >> 1) * 32;

    const float* Wbase = (o0 < DMODEL) ? (Wq + (size_t)o0 * DMODEL)
                                       : (Wkv + (size_t)(o0 - DMODEL) * DMODEL);
    const float* xb = x + (size_t)b * DMODEL * LSEQ;

    const int wrow = t >> 1;
    const int wh   = t & 1;

    float c[4][4][4];
    #pragma unroll
    for (int i = 0; i < 4; i++)
        #pragma unroll
        for (int j = 0; j < 4; j++)
            #pragma unroll
            for (int r = 0; r < 4; r++) c[i][j][r] = 0.f;

    for (int kb = 0; kb < DMODEL; kb += KB) {
        __syncthreads();

        {
            const float4* wp = (const float4*)(Wbase + (size_t)wrow * DMODEL + kb + wh * 16);
            #pragma unroll
            for (int r = 0; r < 4; r++) {
                float4 v = wp[r];
                int k = wh * 16 + r * 4;
                As[(k + 0) * SAST + wrow] = __uint_as_float(f2tf32(v.x));
                As[(k + 1) * SAST + wrow] = __uint_as_float(f2tf32(v.y));
                As[(k + 2) * SAST + wrow] = __uint_as_float(f2tf32(v.z));
                As[(k + 3) * SAST + wrow] = __uint_as_float(f2tf32(v.w));
            }
        }
        #pragma unroll
        for (int r = 0; r < 4; r++) {
            int f = t + r * 256;
            int krow = f >> 5, cc = (f & 31) * 4;
            float4 v = *(const float4*)(xb + (size_t)(kb + krow) * LSEQ + l0 + cc);
            uint4 tv = make_uint4(f2tf32(v.x), f2tf32(v.y), f2tf32(v.z), f2tf32(v.w));
            *(uint4*)&Bs[krow * SAST + cc] = tv;
        }
        __syncthreads();

        #pragma unroll
        for (int ks = 0; ks < 4; ks++) {
            const int k0 = ks * 8 + (lane & 3);
            unsigned a[4][4];
            #pragma unroll
            for (int i = 0; i < 4; i++) {
                int oA = ow + 16 * i + (lane >> 2);
                a[i][0] = __float_as_uint(As[(k0    ) * SAST + oA    ]);
                a[i][1] = __float_as_uint(As[(k0    ) * SAST + oA + 8]);
                a[i][2] = __float_as_uint(As[(k0 + 4) * SAST + oA    ]);
                a[i][3] = __float_as_uint(As[(k0 + 4) * SAST + oA + 8]);
            }
            unsigned bb[4][2];
            #pragma unroll
            for (int j = 0; j < 4; j++) {
                int lB = lw + 8 * j + (lane >> 2);
                bb[j][0] = __float_as_uint(Bs[(k0    ) * SAST + lB]);
                bb[j][1] = __float_as_uint(Bs[(k0 + 4) * SAST + lB]);
            }
            #pragma unroll
            for (int i = 0; i < 4; i++)
                #pragma unroll
                for (int j = 0; j < 4; j++)
                    mma_tf32(c[i][j], a[i][0], a[i][1], a[i][2], a[i][3],
                             bb[j][0], bb[j][1]);
        }
    }

    const int r0  = lane >> 2;
    const int cl0 = 2 * (lane & 3);
    const bool isQ = (o0 < DMODEL);
    const bool isV = (o0 >= 2 * DMODEL);
    const float scale = isQ ? 0.125f : 1.f;
    const int om_base = o0 - (isQ ? 0 : (isV ? 2 * DMODEL : DMODEL));

    if (!isV) {
        float* dst = (isQ ? g_Q : g_K) + (size_t)b * DMODEL * LSEQ;
        #pragma unroll
        for (int i = 0; i < 4; i++) {
            #pragma unroll
            for (int half = 0; half < 2; half++) {
                int om = om_base + ow + 16 * i + r0 + 8 * half;
                float* rowp = dst + (size_t)om * LSEQ + l0 + lw + cl0;
                #pragma unroll
                for (int j = 0; j < 4; j++) {
                    float2 v = make_float2(c[i][j][2 * half] * scale,
                                           c[i][j][2 * half + 1] * scale);
                    *(float2*)&rowp[8 * j] = v;
                }
            }
        }
    } else {
        float* vdst = g_V + (size_t)b * DMODEL * LSEQ;
        #pragma unroll
        for (int i = 0; i < 4; i++) {
            #pragma unroll
            for (int half = 0; half < 2; half++) {
                int om = om_base + ow + 16 * i + r0 + 8 * half;
                int h = om >> 6, d = om & 63;
                float* basep = vdst + (size_t)h * LSEQ * DH + d;
                #pragma unroll
                for (int j = 0; j < 4; j++) {
                    int l = l0 + lw + 8 * j + cl0;
                    basep[(size_t)l * DH]       = c[i][j][2 * half];
                    basep[(size_t)(l + 1) * DH] = c[i][j][2 * half + 1];
                }
            }
        }
    }
}

// ---------------------------------------------------------------------------
// Flash attention v4: tensor-core GEMMs, ALU-lean mainloop.
// vs v3: V pre-converted to tf32 at staging, P stored as tf32 at softmax
// (PV fragment loads are raw LDS), softmax parallelized across all 256
// threads (2 per q row). Numerics identical to v3.
// ---------------------------------------------------------------------------
#define QST 136
#define KST 72
#define QTILE 128
#define ATTN_SMEM ((2 * 64 * QST + 2 * 64 * KST + 64 + 256 + 512) * (int)sizeof(float))

__global__ __launch_bounds__(256, 2)
void attn_kernel(const int* __restrict__ mask, float* __restrict__ out)
{
    extern __shared__ float sm[];
    float* Qts     = sm;                  // [d][q]  64 x QST
    float* Kts     = Qts + 64 * QST;      // [d][k]  64 x KST
    float* Vs      = Kts + 64 * KST;      // [k][d]  64 x KST (tf32 bits)
    float* Sts     = Vs  + 64 * KST;      // [k][q]  64 x QST (S, then tf32 P, then O)
    float* maskf   = Sts + 64 * QST;      // [64]
    float* alpha_s = maskf + 64;          // [128]
    float* l_s     = alpha_s + 128;       // [128]
    float* pm      = l_s + 128;           // [256] partial max
    float* ps      = pm + 256;            // [256] partial sum

    const int t    = threadIdx.x;
    const int lane = t & 31;
    const int wid  = t >> 5;
    const int gid  = lane >> 2;
    const int tig  = lane & 3;
    const int qw   = (wid & 3) * 32;
    const int kdw  = (wid >> 2) * 32;
    const int q0 = blockIdx.x * QTILE;
    const int bh = blockIdx.y;
    const int b  = bh >> 4;
    const int h  = bh & 15;

    const int srow  = t & 127;            // softmax row
    const int shalf = t >> 7;             // softmax k-half
    const int sk0   = shalf * 32;

    const float* Qb = g_Q + (size_t)bh * DH * LSEQ;
    const float* Kb = g_K + (size_t)bh * DH * LSEQ;
    const float* Vb = g_V + (size_t)bh * LSEQ * DH;

    #pragma unroll
    for (int r = 0; r < 8; r++) {
        int f = t + r * 256;
        int row = f >> 5, c = (f & 31) * 4;
        *(float4*)&Qts[row * QST + c] =
            *(const float4*)(Qb + (size_t)row * LSEQ + q0 + c);
    }

    float oacc[2][4][4];
    #pragma unroll
    for (int mi = 0; mi < 2; mi++)
        #pragma unroll
        for (int nj = 0; nj < 4; nj++)
            #pragma unroll
            for (int r = 0; r < 4; r++) oacc[mi][nj][r] = 0.f;

    float m_run = __int_as_float(0xff800000);
    float l_run = 0.f;

    for (int k0 = 0; k0 < LSEQ; k0 += 64) {
        __syncthreads();

        #pragma unroll
        for (int r = 0; r < 4; r++) {
            int f = t + r * 256;
            int row = f >> 4, c = (f & 15) * 4;
            *(float4*)&Kts[row * KST + c] =
                *(const float4*)(Kb + (size_t)row * LSEQ + k0 + c);
            float4 v = *(const float4*)(Vb + ((size_t)(k0 + row) << 6) + c);
            uint4 tv = make_uint4(f2tf32(v.x), f2tf32(v.y), f2tf32(v.z), f2tf32(v.w));
            *(uint4*)&Vs[row * KST + c] = tv;
        }
        if (t < 64) maskf[t] = (float)mask[b * LSEQ + k0 + t];
        __syncthreads();

        // ---- S = Q K^T  (tf32x2: hi*hi + hi*lo + lo*hi) ----
        float sC[2][4][4];
        #pragma unroll
        for (int mi = 0; mi < 2; mi++)
            #pragma unroll
            for (int nj = 0; nj < 4; nj++)
                #pragma unroll
                for (int r = 0; r < 4; r++) sC[mi][nj][r] = 0.f;

        #pragma unroll
        for (int ks = 0; ks < 8; ks++) {
            const int dA = ks * 8 + tig;
            unsigned ahi[2][4], alo[2][4];
            #pragma unroll
            for (int mi = 0; mi < 2; mi++) {
                int qa = qw + 16 * mi + gid;
                tf32_split(Qts[dA * QST + qa],           ahi[mi][0], alo[mi][0]);
                tf32_split(Qts[dA * QST + qa + 8],       ahi[mi][1], alo[mi][1]);
                tf32_split(Qts[(dA + 4) * QST + qa],     ahi[mi][2], alo[mi][2]);
                tf32_split(Qts[(dA + 4) * QST + qa + 8], ahi[mi][3], alo[mi][3]);
            }
            #pragma unroll
            for (int nj = 0; nj < 4; nj++) {
                int kc = kdw + 8 * nj + gid;
                unsigned b0h, b0l, b1h, b1l;
                tf32_split(Kts[dA * KST + kc],       b0h, b0l);
                tf32_split(Kts[(dA + 4) * KST + kc], b1h, b1l);
                #pragma unroll
                for (int mi = 0; mi < 2; mi++) {
                    mma_tf32(sC[mi][nj], ahi[mi][0], ahi[mi][1], ahi[mi][2], ahi[mi][3], b0h, b1h);
                    mma_tf32(sC[mi][nj], ahi[mi][0], ahi[mi][1], ahi[mi][2], ahi[mi][3], b0l, b1l);
                    mma_tf32(sC[mi][nj], alo[mi][0], alo[mi][1], alo[mi][2], alo[mi][3], b0h, b1h);
                }
            }
        }

        // ---- mask + store S transposed: Sts[k][q] ----
        #pragma unroll
        for (int mi = 0; mi < 2; mi++) {
            int qa = qw + 16 * mi + gid;
            #pragma unroll
            for (int nj = 0; nj < 4; nj++) {
                int kc = kdw + 8 * nj + 2 * tig;
                float km0 = maskf[kc], km1 = maskf[kc + 1];
                Sts[kc * QST + qa]           = (km0 > 0.5f) ? sC[mi][nj][0] : -1e30f;
                Sts[(kc + 1) * QST + qa]     = (km1 > 0.5f) ? sC[mi][nj][1] : -1e30f;
                Sts[kc * QST + qa + 8]       = (km0 > 0.5f) ? sC[mi][nj][2] : -1e30f;
                Sts[(kc + 1) * QST + qa + 8] = (km1 > 0.5f) ? sC[mi][nj][3] : -1e30f;
            }
        }
        __syncthreads();

        // ---- online softmax, 2 threads per q row ----
        {
            float pmax = __int_as_float(0xff800000);
            #pragma unroll 8
            for (int k = 0; k < 32; k++)
                pmax = fmaxf(pmax, Sts[(sk0 + k) * QST + srow]);
            pm[t] = pmax;
        }
        __syncthreads();
        {
            float tmax = fmaxf(pm[srow], pm[128 + srow]);
            float mn  = fmaxf(m_run, tmax);
            float al  = __expf(m_run - mn);
            float sum = 0.f;
            #pragma unroll 8
            for (int k = 0; k < 32; k++) {
                float p = __expf(Sts[(sk0 + k) * QST + srow] - mn);
                Sts[(sk0 + k) * QST + srow] = __uint_as_float(f2tf32(p));
                sum += p;
            }
            ps[t] = sum;
            if (shalf == 0) alpha_s[srow] = al;
            m_run = mn;
            l_run *= al;
        }
        __syncthreads();
        l_run += ps[srow] + ps[128 + srow];

        // ---- rescale O, then O += P @ V (tf32, raw LDS of pre-converted bits) ----
        #pragma unroll
        for (int mi = 0; mi < 2; mi++) {
            int qa = qw + 16 * mi + gid;
            float al0 = alpha_s[qa], al1 = alpha_s[qa + 8];
            #pragma unroll
            for (int nj = 0; nj < 4; nj++) {
                oacc[mi][nj][0] *= al0;
                oacc[mi][nj][1] *= al0;
                oacc[mi][nj][2] *= al1;
                oacc[mi][nj][3] *= al1;
            }
        }

        #pragma unroll
        for (int ks = 0; ks < 8; ks++) {
            const int kA = ks * 8 + tig;
            unsigned pa[2][4];
            #pragma unroll
            for (int mi = 0; mi < 2; mi++) {
                int qa = qw + 16 * mi + gid;
                pa[mi][0] = __float_as_uint(Sts[kA * QST + qa]);
                pa[mi][1] = __float_as_uint(Sts[kA * QST + qa + 8]);
                pa[mi][2] = __float_as_uint(Sts[(kA + 4) * QST + qa]);
                pa[mi][3] = __float_as_uint(Sts[(kA + 4) * QST + qa + 8]);
            }
            #pragma unroll
            for (int nj = 0; nj < 4; nj++) {
                int dc = kdw + 8 * nj + gid;
                unsigned v0 = __float_as_uint(Vs[kA * KST + dc]);
                unsigned v1 = __float_as_uint(Vs[(kA + 4) * KST + dc]);
                #pragma unroll
                for (int mi = 0; mi < 2; mi++)
                    mma_tf32(oacc[mi][nj], pa[mi][0], pa[mi][1], pa[mi][2], pa[mi][3], v0, v1);
            }
        }
    }

    if (shalf == 0) l_s[srow] = l_run;
    __syncthreads();

    // ---- normalize, stage O[d][q] into Sts ----
    #pragma unroll
    for (int mi = 0; mi < 2; mi++) {
        int qa = qw + 16 * mi + gid;
        float inv0 = 1.f / l_s[qa];
        float inv1 = 1.f / l_s[qa + 8];
        #pragma unroll
        for (int nj = 0; nj < 4; nj++) {
            int dc = kdw + 8 * nj + 2 * tig;
            Sts[dc * QST + qa]           = oacc[mi][nj][0] * inv0;
            Sts[(dc + 1) * QST + qa]     = oacc[mi][nj][1] * inv0;
            Sts[dc * QST + qa + 8]       = oacc[mi][nj][2] * inv1;
            Sts[(dc + 1) * QST + qa + 8] = oacc[mi][nj][3] * inv1;
        }
    }
    __syncthreads();

    // ---- coalesced write: out[b][h*64+d][q0+q] ----
    float* ob = out + ((size_t)b * DMODEL + h * DH) * LSEQ;
    #pragma unroll
    for (int r = 0; r < 8; r++) {
        int f = t + r * 256;
        int row = f >> 5, c = (f & 31) * 4;
        *(float4*)(ob + (size_t)row * LSEQ + q0 + c) =
            *(float4*)&Sts[row * QST + c];
    }
}

// ---------------------------------------------------------------------------
extern "C" void kernel_launch(void* const* d_in, const int* in_sizes, int n_in,
                              void* d_out, int out_size)
{
    const float* x    = (const float*)d_in[0];
    const float* Wq   = (const float*)d_in[1];
    const float* Wkv  = (const float*)d_in[2];
    const int*   mask = (const int*)d_in[3];
    float* out = (float*)d_out;

    cudaFuncSetAttribute(attn_kernel,
                         cudaFuncAttributeMaxDynamicSharedMemorySize, ATTN_SMEM);

    proj_kernel<<<dim3(LSEQ / 128, (3 * DMODEL) / 128, BATCH), 256>>>(x, Wq, Wkv);
    attn_kernel<<<dim3(LSEQ / QTILE, BATCH * HEADS), 256, ATTN_SMEM>>>(mask, out);
}